// round 3
// baseline (speedup 1.0000x reference)
#include <cuda_runtime.h>

// Fully fused shift + H-conv(128->8 via w1) + W-conv(8->128 via w2), (1,128,56,56) fp32.
// Grid (2 n-halves, 56 rows), 512 threads. Each x load feeds all 4 k4 outputs.
//
// Stage 1: inter[k4][o][nl] = sum_{i<64,j<3} w1[k4,i,j] * X(2i+o, m+j-1, nb-1+nl)
//   X(c,h,n) = x[c][(h-1+56)%56][n] if 0<=h<56 else 0  (roll(+1) in H, zero-pad H)
// Stage 2: out[i32*4+k4][m][nb+n2] = sum_{o,kk} w2[i32,o,kk] * inter[k4][o][n2+kk]  (zero-pad W)

#define HH 56
#define WW 56
#define THREADS 512

__global__ __launch_bounds__(THREADS)
void fused_shift_conv_v3(const float* __restrict__ x,
                         const float* __restrict__ w1,
                         const float* __restrict__ w2,
                         float* __restrict__ out)
{
    __shared__ float w1s[768];            // [k4][i64][j3]
    __shared__ float w2s[192];            // [i32][o2][kk3]
    __shared__ float psum[16 * 4 * 32];   // [s][k4][lane]
    __shared__ float inter_s[8 * 32];     // [k4*2+o][lane], lane nl -> global n = nb-1+nl

    const int tid = threadIdx.x;
    const int nb  = blockIdx.x * 28;      // 0 or 28
    const int m   = blockIdx.y;           // 0..55

    for (int i = tid; i < 768; i += THREADS) w1s[i] = w1[i];
    if (tid < 192) w2s[tid] = w2[tid];
    __syncthreads();

    // ---------------- Phase 1: partials, coalesced over n ----------------
    const int l  = tid & 31;              // lane -> inter column nl (0..29 valid)
    const int s  = tid >> 5;              // 0..15 : s = ig*2 + o
    const int o  = s & 1;
    const int ig = s >> 1;                // i-eighth (8 i values)
    const int ng = nb - 1 + l;            // global n for this inter column

    float msk[3];
    int   hoff[3];
    #pragma unroll
    for (int j = 0; j < 3; ++j) {
        const int hh = m + j - 1;                  // pre-roll coordinate
        msk[j]  = (hh >= 0 && hh < HH) ? 1.f : 0.f;
        hoff[j] = ((hh + 55) % HH) * WW;           // rolled source row offset
    }

    float a0 = 0.f, a1 = 0.f, a2 = 0.f, a3 = 0.f;
    if (l < 30 && ng >= 0 && ng < WW) {
        const float* xn = x + ng;
        #pragma unroll
        for (int ii = 0; ii < 8; ++ii) {
            const int i = ig * 8 + ii;
            const int c = 2 * i + o;
            const float* xb = xn + c * (HH * WW);
            const float* wb = w1s + i * 3;
            #pragma unroll
            for (int j = 0; j < 3; ++j) {
                const float xv = __ldg(xb + hoff[j]) * msk[j];
                a0 = fmaf(wb[j],       xv, a0);
                a1 = fmaf(wb[192 + j], xv, a1);
                a2 = fmaf(wb[384 + j], xv, a2);
                a3 = fmaf(wb[576 + j], xv, a3);
            }
        }
    }
    psum[(s * 4 + 0) * 32 + l] = a0;
    psum[(s * 4 + 1) * 32 + l] = a1;
    psum[(s * 4 + 2) * 32 + l] = a2;
    psum[(s * 4 + 3) * 32 + l] = a3;
    __syncthreads();

    // reduce the 8 i-eighths per (k4, o) -> inter_s
    if (tid < 256) {
        const int ll = tid & 31;
        const int ko = tid >> 5;          // k4*2 + o
        const int k  = ko >> 1;
        const int oo = ko & 1;
        float sum = 0.f;
        #pragma unroll
        for (int gg = 0; gg < 8; ++gg)
            sum += psum[((gg * 2 + oo) * 4 + k) * 32 + ll];
        inter_s[ko * 32 + ll] = sum;
    }
    __syncthreads();

    // ---------------- Phase 2: 128 channels x 28 cols ----------------
    #pragma unroll
    for (int t = 0; t < 7; ++t) {
        const int idx = tid + t * THREADS;        // 0..3583
        const int n2  = idx % 28;
        const int co  = idx / 28;                 // 0..127, co = i32*4 + k4
        const int i32 = co >> 2;
        const int k4  = co & 3;

        const float* wb = w2s + i32 * 6;
        float acc = 0.f;
        #pragma unroll
        for (int oo = 0; oo < 2; ++oo) {
            const float* ib = inter_s + (k4 * 2 + oo) * 32 + n2;  // taps n2..n2+2
            #pragma unroll
            for (int kk = 0; kk < 3; ++kk)
                acc = fmaf(wb[oo * 3 + kk], ib[kk], acc);
        }
        out[co * (HH * WW) + m * WW + nb + n2] = acc;
    }
}

extern "C" void kernel_launch(void* const* d_in, const int* in_sizes, int n_in,
                              void* d_out, int out_size)
{
    const float* x  = (const float*)d_in[0];   // (1,128,56,56)
    const float* w1 = (const float*)d_in[1];   // (4,64,3)
    const float* w2 = (const float*)d_in[2];   // (32,2,3)
    float* out = (float*)d_out;                // (1,128,56,56)

    dim3 grid(2, HH);                          // 112 blocks
    fused_shift_conv_v3<<<grid, THREADS>>>(x, w1, w2, out);
}

// round 4
// speedup vs baseline: 1.0323x; 1.0323x over previous
#include <cuda_runtime.h>

// Fully fused shift + H-conv(128->8 via w1) + W-conv(8->128 via w2), (1,128,56,56) fp32.
// Grid (4 n-quarters, 56 rows) = 224 blocks, 512 threads.
// Each x load feeds all 4 k4 outputs (k-fusion); i split 16 ways for concurrency.
//
// Stage 1: inter[k4][o][l] = sum_{i<64,j<3} w1[k4,i,j] * X(2i+o, m+j-1, nb-1+l)
//   X(c,h,n) = x[c][(h-1+56)%56][n] if 0<=h<56 else 0  (roll(+1) in H, zero-pad H)
// Stage 2: out[i32*4+k4][m][nb+n2] = sum_{o,kk} w2[i32,o,kk] * inter[k4][o][n2+kk] (zero-pad W)

#define HH 56
#define WW 56
#define TNO 14            // output cols per block
#define TNL 16            // inter cols per block (14 + 2 halo)
#define THREADS 512

__global__ __launch_bounds__(THREADS)
void fused_shift_conv_v4(const float* __restrict__ x,
                         const float* __restrict__ w1,
                         const float* __restrict__ w2,
                         float* __restrict__ out)
{
    __shared__ float w1s[768];                 // [k4][i64][j3]
    __shared__ float w2s[192];                 // [i32][o2][kk3]
    __shared__ float psum[32 * 4 * TNL];       // [s][k4][l]  (8 KB)
    __shared__ float inter_s[8 * TNL];         // [k4*2+o][l]

    const int tid = threadIdx.x;
    const int nb  = blockIdx.x * TNO;          // 0,14,28,42
    const int m   = blockIdx.y;                // 0..55

    if (tid < 256) {
        w1s[tid]       = w1[tid];
        w1s[tid + 256] = w1[tid + 256];
        w1s[tid + 512] = w1[tid + 512];
        if (tid < 192) w2s[tid] = w2[tid];
    }
    __syncthreads();

    // ---------------- Phase 1: partials, coalesced over n ----------------
    const int l  = tid & (TNL - 1);            // inter column 0..15
    const int s  = tid >> 4;                   // 0..31 : s = ig*2 + o
    const int o  = s & 1;
    const int ig = s >> 1;                     // 0..15, 4 i-values each
    const int ng = nb - 1 + l;                 // global n for this inter column

    float msk[3];
    int   hoff[3];
    #pragma unroll
    for (int j = 0; j < 3; ++j) {
        const int hh = m + j - 1;                       // pre-roll coordinate
        msk[j]  = (hh >= 0 && hh < HH) ? 1.f : 0.f;
        hoff[j] = ((hh + 55) % HH) * WW;                // rolled source row offset
    }

    float a0 = 0.f, a1 = 0.f, a2 = 0.f, a3 = 0.f;
    if (ng >= 0 && ng < WW) {
        const float* xn = x + ng;
        #pragma unroll
        for (int ii = 0; ii < 4; ++ii) {
            const int i = ig * 4 + ii;
            const int c = 2 * i + o;
            const float* xb = xn + c * (HH * WW);
            const float* wb = w1s + i * 3;
            #pragma unroll
            for (int j = 0; j < 3; ++j) {
                const float xv = __ldg(xb + hoff[j]) * msk[j];
                a0 = fmaf(wb[j],       xv, a0);
                a1 = fmaf(wb[192 + j], xv, a1);
                a2 = fmaf(wb[384 + j], xv, a2);
                a3 = fmaf(wb[576 + j], xv, a3);
            }
        }
    }
    psum[(s * 4 + 0) * TNL + l] = a0;
    psum[(s * 4 + 1) * TNL + l] = a1;
    psum[(s * 4 + 2) * TNL + l] = a2;
    psum[(s * 4 + 3) * TNL + l] = a3;
    __syncthreads();

    // reduce the 16 i-groups per (k4, o, l) -> inter_s
    if (tid < 128) {
        const int ll = tid & (TNL - 1);
        const int ko = tid >> 4;               // k4*2 + o
        const int k  = ko >> 1;
        const int oo = ko & 1;
        float sum = 0.f;
        #pragma unroll
        for (int gg = 0; gg < 16; ++gg)
            sum += psum[((gg * 2 + oo) * 4 + k) * TNL + ll];
        inter_s[ko * TNL + ll] = sum;
    }
    __syncthreads();

    // ---------------- Phase 2: 128 channels x 14 cols ----------------
    #pragma unroll
    for (int t = 0; t < 4; ++t) {
        const int idx = tid + t * THREADS;     // 0..2047, use 0..1791
        if (idx < 128 * TNO) {
            const int n2  = idx % TNO;         // 0..13
            const int co  = idx / TNO;         // 0..127, co = i32*4 + k4
            const int i32 = co >> 2;
            const int k4  = co & 3;

            const float* wb = w2s + i32 * 6;
            float acc = 0.f;
            #pragma unroll
            for (int oo = 0; oo < 2; ++oo) {
                const float* ib = inter_s + (k4 * 2 + oo) * TNL + n2;   // taps n2..n2+2
                #pragma unroll
                for (int kk = 0; kk < 3; ++kk)
                    acc = fmaf(wb[oo * 3 + kk], ib[kk], acc);
            }
            out[co * (HH * WW) + m * WW + nb + n2] = acc;
        }
    }
}

extern "C" void kernel_launch(void* const* d_in, const int* in_sizes, int n_in,
                              void* d_out, int out_size)
{
    const float* x  = (const float*)d_in[0];   // (1,128,56,56)
    const float* w1 = (const float*)d_in[1];   // (4,64,3)
    const float* w2 = (const float*)d_in[2];   // (32,2,3)
    float* out = (float*)d_out;                // (1,128,56,56)

    dim3 grid(WW / TNO, HH);                   // (4, 56) = 224 blocks
    fused_shift_conv_v4<<<grid, THREADS>>>(x, w1, w2, out);
}

// round 6
// speedup vs baseline: 1.0627x; 1.0295x over previous
#include <cuda_runtime.h>

// Fully fused shift + H-conv(128->8 via w1) + W-conv(8->128 via w2), (1,128,56,56) fp32.
// Grid (8 n-eighths, 56 rows) = 448 blocks, 288 threads -> ~3 blocks/SM, single wave.
// x values prefetched to registers BEFORE the weight barrier (overlaps the two L2 trips).
//
// Stage 1: inter[k4][o][l] = sum_{i<64,j<3} w1[k4,i,j] * X(2i+o, m+j-1, nb-1+l)
//   X(c,h,n) = x[c][(h-1+56)%56][n] if 0<=h<56 else 0  (roll(+1) in H, zero-pad H)
// Stage 2: out[i32*4+k4][m][nb+n2] = sum_{o,kk} w2[i32,o,kk] * inter[k4][o][n2+kk] (zero-pad W)

#define HH 56
#define WW 56
#define TNO 7             // output cols per block
#define TNL 9             // inter cols per block (7 + 2 halo)
#define THREADS 288       // 32 s-groups x 9 lanes

__global__ __launch_bounds__(THREADS)
void fused_shift_conv_v5(const float* __restrict__ x,
                         const float* __restrict__ w1,
                         const float* __restrict__ w2,
                         float* __restrict__ out)
{
    __shared__ float w1s[768];               // [k4][i64][j3]
    __shared__ float w2s[192];               // [i32][o2][kk3]
    __shared__ float psum[32 * 4 * TNL];     // [s][k4][l]
    __shared__ float inter_s[8 * TNL];       // [k4*2+o][l]

    const int tid = threadIdx.x;
    const int nb  = blockIdx.x * TNO;        // 0..49
    const int m   = blockIdx.y;              // 0..55

    // thread mapping
    const int l  = tid % TNL;                // inter column 0..8
    const int s  = tid / TNL;                // 0..31 : s = ig*2 + o
    const int o  = s & 1;
    const int ig = s >> 1;                   // 0..15, 4 i-values each
    const int ng = nb - 1 + l;               // global n for this inter column
    const bool nvalid = (ng >= 0) && (ng < WW);
    const int ngc = nvalid ? ng : 0;         // clamped, always in-bounds

    // ---- prefetch x into registers (independent of smem weights; overlaps) ----
    float msk[3];
    int   hoff[3];
    #pragma unroll
    for (int j = 0; j < 3; ++j) {
        const int hh = m + j - 1;                     // pre-roll coordinate
        msk[j]  = (hh >= 0 && hh < HH) ? 1.f : 0.f;
        hoff[j] = ((hh + 55) % HH) * WW;              // rolled source row offset
    }

    float xv[4][3];
    {
        const float* xn = x + ngc;
        #pragma unroll
        for (int ii = 0; ii < 4; ++ii) {
            const int c = 2 * (ig * 4 + ii) + o;
            const float* xb = xn + c * (HH * WW);
            #pragma unroll
            for (int j = 0; j < 3; ++j)
                xv[ii][j] = __ldg(xb + hoff[j]);
        }
    }

    // ---- stage weights to smem (overlapped with the x loads above) ----
    for (int i = tid; i < 768; i += THREADS) w1s[i] = w1[i];
    if (tid < 192) w2s[tid] = w2[tid];

    // fold masks into the register values
    const float nm = nvalid ? 1.f : 0.f;
    #pragma unroll
    for (int ii = 0; ii < 4; ++ii) {
        xv[ii][0] *= msk[0] * nm;
        xv[ii][1] *= msk[1] * nm;
        xv[ii][2] *= msk[2] * nm;
    }

    __syncthreads();

    // ---------------- Phase 1: FMAs from registers ----------------
    float a0 = 0.f, a1 = 0.f, a2 = 0.f, a3 = 0.f;
    #pragma unroll
    for (int ii = 0; ii < 4; ++ii) {
        const float* wb = w1s + (ig * 4 + ii) * 3;
        #pragma unroll
        for (int j = 0; j < 3; ++j) {
            const float v = xv[ii][j];
            a0 = fmaf(wb[j],       v, a0);
            a1 = fmaf(wb[192 + j], v, a1);
            a2 = fmaf(wb[384 + j], v, a2);
            a3 = fmaf(wb[576 + j], v, a3);
        }
    }
    psum[(s * 4 + 0) * TNL + l] = a0;
    psum[(s * 4 + 1) * TNL + l] = a1;
    psum[(s * 4 + 2) * TNL + l] = a2;
    psum[(s * 4 + 3) * TNL + l] = a3;
    __syncthreads();

    // reduce the 16 i-groups per (k4, o, l) -> inter_s
    if (tid < 8 * TNL) {
        const int ll = tid % TNL;
        const int ko = tid / TNL;            // 0..7
        const int k  = ko >> 1;
        const int oo = ko & 1;
        float sum = 0.f;
        #pragma unroll
        for (int gg = 0; gg < 16; ++gg)
            sum += psum[((gg * 2 + oo) * 4 + k) * TNL + ll];
        inter_s[(k * 2 + oo) * TNL + ll] = sum;
    }
    __syncthreads();

    // ---------------- Phase 2: 128 channels x 7 cols ----------------
    #pragma unroll
    for (int t = 0; t < 4; ++t) {
        const int idx = tid + t * THREADS;   // 0..1151, use 0..895
        if (idx < 128 * TNO) {
            const int n2  = idx % TNO;       // 0..6
            const int co  = idx / TNO;       // 0..127, co = i32*4 + k4
            const int i32 = co >> 2;
            const int k4  = co & 3;

            const float* wb = w2s + i32 * 6;
            float acc = 0.f;
            #pragma unroll
            for (int oo = 0; oo < 2; ++oo) {
                const float* ib = inter_s + (k4 * 2 + oo) * TNL + n2;   // taps n2..n2+2
                #pragma unroll
                for (int kk = 0; kk < 3; ++kk)
                    acc = fmaf(wb[oo * 3 + kk], ib[kk], acc);
            }
            out[co * (HH * WW) + m * WW + nb + n2] = acc;
        }
    }
}

extern "C" void kernel_launch(void* const* d_in, const int* in_sizes, int n_in,
                              void* d_out, int out_size)
{
    const float* x  = (const float*)d_in[0];   // (1,128,56,56)
    const float* w1 = (const float*)d_in[1];   // (4,64,3)
    const float* w2 = (const float*)d_in[2];   // (32,2,3)
    float* out = (float*)d_out;                // (1,128,56,56)

    dim3 grid(WW / TNO, HH);                   // (8, 56) = 448 blocks
    fused_shift_conv_v5<<<grid, THREADS>>>(x, w1, w2, out);
}